// round 16
// baseline (speedup 1.0000x reference)
#include <cuda_runtime.h>
#include <cuda_fp16.h>
#include <math.h>
#include <stdint.h>

constexpr int B_    = 2;
constexpr int NQ    = 2048;
constexpr int NKV   = 2048;
constexpr int D     = 1024;
constexpr int INNER = 1024;
constexpr int HEADS = 16;
constexpr int DIMH  = 64;

constexpr int ROWS = B_ * NQ; // 4096
constexpr float SCALE_LOG2E = 0.125f * 1.4426950408889634f;

// Scratch (allocation-free rule: __device__ globals)
__device__ __half g_Q[ROWS * INNER];
__device__ __half g_K[ROWS * INNER];
__device__ __half g_V[ROWS * INNER];
__device__ __half g_A[ROWS * INNER];
__device__ __half g_PA[ROWS * D];
__device__ __half g_PX[ROWS * D];
__device__ __half g_WQ[D * INNER];   // transposed weights [N][K]
__device__ __half g_WK[D * INNER];
__device__ __half g_WV[D * INNER];
__device__ __half g_WO[INNER * D];
// split-KV partials
constexpr int ASPLIT = 4;
__device__ float g_OP[(size_t)ASPLIT * ROWS * INNER];   // unnormalized O partials
__device__ float g_SUM[(size_t)ASPLIT * ROWS * HEADS];  // row-sum partials

// ---------------------------------------------------------------------------
// helpers
// ---------------------------------------------------------------------------
__device__ __forceinline__ void cp_async16(void* dst, const void* src) {
    uint32_t s = (uint32_t)__cvta_generic_to_shared(dst);
    asm volatile("cp.async.cg.shared.global [%0], [%1], 16;\n" :: "r"(s), "l"(src));
}
__device__ __forceinline__ void cp_commit() { asm volatile("cp.async.commit_group;\n"); }

__device__ __forceinline__ float ex2(float x) {
    float r; asm("ex2.approx.ftz.f32 %0, %1;" : "=f"(r) : "f"(x)); return r;
}
__device__ __forceinline__ uint32_t pack2(float lo, float hi) {
    uint32_t r;
    asm("cvt.rn.f16x2.f32 %0, %1, %2;" : "=r"(r) : "f"(hi), "f"(lo));
    return r;
}

__device__ __forceinline__ void mma_f16(float* c, const uint32_t* a, uint32_t b0, uint32_t b1) {
    asm volatile(
        "mma.sync.aligned.m16n8k16.row.col.f32.f16.f16.f32 "
        "{%0,%1,%2,%3}, {%4,%5,%6,%7}, {%8,%9}, {%0,%1,%2,%3};\n"
        : "+f"(c[0]), "+f"(c[1]), "+f"(c[2]), "+f"(c[3])
        : "r"(a[0]), "r"(a[1]), "r"(a[2]), "r"(a[3]), "r"(b0), "r"(b1));
}

__device__ __forceinline__ void ldmx4(uint32_t& r0, uint32_t& r1, uint32_t& r2, uint32_t& r3,
                                      const void* p) {
    uint32_t a = (uint32_t)__cvta_generic_to_shared(p);
    asm volatile("ldmatrix.sync.aligned.m8n8.x4.shared.b16 {%0,%1,%2,%3}, [%4];"
                 : "=r"(r0), "=r"(r1), "=r"(r2), "=r"(r3) : "r"(a));
}
__device__ __forceinline__ void ldmx4_trans(uint32_t& r0, uint32_t& r1, uint32_t& r2, uint32_t& r3,
                                            const void* p) {
    uint32_t a = (uint32_t)__cvta_generic_to_shared(p);
    asm volatile("ldmatrix.sync.aligned.m8n8.x4.trans.shared.b16 {%0,%1,%2,%3}, [%4];"
                 : "=r"(r0), "=r"(r1), "=r"(r2), "=r"(r3) : "r"(a));
}
__device__ __forceinline__ void ldmx2_trans(uint32_t& r0, uint32_t& r1, const void* p) {
    uint32_t a = (uint32_t)__cvta_generic_to_shared(p);
    asm volatile("ldmatrix.sync.aligned.m8n8.x2.trans.shared.b16 {%0,%1}, [%2];"
                 : "=r"(r0), "=r"(r1) : "r"(a));
}

// ---------------------------------------------------------------------------
// prep kernels
// ---------------------------------------------------------------------------
__global__ void cvth4(__half* __restrict__ d0, const float4* __restrict__ s0,
                      __half* __restrict__ d1, const float4* __restrict__ s1,
                      int n4, int stride) {
    const int base = blockIdx.x * blockDim.x + threadIdx.x;
    const float4* s = blockIdx.y ? s1 : s0;
    __half* d = blockIdx.y ? d1 : d0;
    float4 v[4];
#pragma unroll
    for (int k = 0; k < 4; k++) {
        const int i = base + k * stride;
        v[k] = s[i];
    }
#pragma unroll
    for (int k = 0; k < 4; k++) {
        const int i = base + k * stride;
        uint2 o;
        o.x = pack2(v[k].x, v[k].y);
        o.y = pack2(v[k].z, v[k].w);
        *reinterpret_cast<uint2*>(d + 4 * (size_t)i) = o;
    }
}

__global__ void transpose_cvt4(__half* __restrict__ d0, const float* __restrict__ s0,
                               __half* __restrict__ d1, const float* __restrict__ s1,
                               __half* __restrict__ d2, const float* __restrict__ s2,
                               __half* __restrict__ d3, const float* __restrict__ s3) {
    __shared__ float t[32][33];
    const int z = blockIdx.z;
    const float* src = (z == 0) ? s0 : (z == 1) ? s1 : (z == 2) ? s2 : s3;
    __half* dst = (z == 0) ? d0 : (z == 1) ? d1 : (z == 2) ? d2 : d3;
    const int n0 = blockIdx.x * 32;
    const int k0 = blockIdx.y * 32;
    const int tx = threadIdx.x, ty = threadIdx.y;
#pragma unroll
    for (int i = 0; i < 4; i++)
        t[ty + i * 8][tx] = src[(size_t)(k0 + ty + i * 8) * 1024 + n0 + tx];
    __syncthreads();
#pragma unroll
    for (int i = 0; i < 4; i++)
        dst[(size_t)(n0 + ty + i * 8) * 1024 + k0 + tx] = __float2half_rn(t[tx][ty + i * 8]);
}

// ---------------------------------------------------------------------------
// fp16 GEMM (round-9 best, unchanged): BM=BN=128, BK=32, 4-stage cp.async.
// ---------------------------------------------------------------------------
constexpr int HG_LD = 40;
constexpr int HG_TILE = 128 * HG_LD;
constexpr int HG_STAGES = 4;
constexpr int HG_SMEM = HG_STAGES * 2 * HG_TILE * 2; // 81920 B

template <bool QKV, bool HALF_OUT, bool BIAS>
__global__ __launch_bounds__(256, 2)
void hgemm(const __half* __restrict__ A0, const __half* __restrict__ W0, void* __restrict__ C0,
           const __half* __restrict__ A1, const __half* __restrict__ W1, void* __restrict__ C1,
           const __half* __restrict__ A2, const __half* __restrict__ W2, void* __restrict__ C2,
           const float* __restrict__ bias, int M, int N, int K, float oscale0) {
    extern __shared__ __half sh[];

    const __half* A = A0; const __half* WT = W0; void* Cv = C0;
    float oscale = oscale0;
    if (QKV) {
        const int z = blockIdx.z;
        if (z == 1) { A = A1; WT = W1; Cv = C1; oscale = 1.0f; }
        else if (z == 2) { A = A2; WT = W2; Cv = C2; oscale = 1.0f; }
    }

    const int tid  = threadIdx.x;
    const int wid  = tid >> 5;
    const int lane = tid & 31;
    const int g    = lane >> 2;
    const int tig  = lane & 3;
    const int wm = wid >> 1;
    const int wn = wid & 1;
    const int bm0 = blockIdx.y * 128;
    const int bn0 = blockIdx.x * 128;
    const int lmr = lane & 15;
    const int lmc = (lane >> 4) * 8;

    float acc[2][8][4];
#pragma unroll
    for (int mi = 0; mi < 2; mi++)
#pragma unroll
        for (int nb = 0; nb < 8; nb++)
#pragma unroll
            for (int e = 0; e < 4; e++) acc[mi][nb][e] = 0.0f;

    auto load_tiles = [&](int buf, int k0) {
#pragma unroll
        for (int i = 0; i < 2; i++) {
            const int idx = tid + i * 256;
            const int r = idx >> 2, c = idx & 3;
            cp_async16(&sh[buf * 2 * HG_TILE + r * HG_LD + c * 8],
                       &A[(size_t)(bm0 + r) * K + k0 + c * 8]);
        }
#pragma unroll
        for (int i = 0; i < 2; i++) {
            const int idx = tid + i * 256;
            const int r = idx >> 2, c = idx & 3;
            cp_async16(&sh[buf * 2 * HG_TILE + HG_TILE + r * HG_LD + c * 8],
                       &WT[(size_t)(bn0 + r) * K + k0 + c * 8]);
        }
    };

    const int KT = K / 32;
    load_tiles(0, 0);  cp_commit();
    load_tiles(1, 32); cp_commit();
    load_tiles(2, 64); cp_commit();

    for (int t = 0; t < KT; t++) {
        const int buf = t & 3;
        asm volatile("cp.async.wait_group 2;\n");
        __syncthreads();
        if (t + 3 < KT) { load_tiles((t + 3) & 3, (t + 3) * 32); cp_commit(); }

        const __half* Ab = sh + buf * 2 * HG_TILE;
        const __half* Bb = Ab + HG_TILE;
#pragma unroll
        for (int ks = 0; ks < 2; ks++) {
            uint32_t a[2][4];
            uint32_t b[4][4];
#pragma unroll
            for (int mi = 0; mi < 2; mi++)
                ldmx4(a[mi][0], a[mi][1], a[mi][2], a[mi][3],
                      Ab + (wm * 32 + mi * 16 + lmr) * HG_LD + ks * 16 + lmc);
#pragma unroll
            for (int nbp = 0; nbp < 4; nbp++)
                ldmx4(b[nbp][0], b[nbp][1], b[nbp][2], b[nbp][3],
                      Bb + (wn * 64 + nbp * 16 + lmr) * HG_LD + ks * 16 + lmc);
#pragma unroll
            for (int nbp = 0; nbp < 4; nbp++)
#pragma unroll
                for (int mi = 0; mi < 2; mi++) {
                    mma_f16(acc[mi][2 * nbp],     a[mi], b[nbp][0], b[nbp][2]);
                    mma_f16(acc[mi][2 * nbp + 1], a[mi], b[nbp][1], b[nbp][3]);
                }
        }
    }

#pragma unroll
    for (int mi = 0; mi < 2; mi++) {
        const int row0 = bm0 + wm * 32 + mi * 16 + g;
#pragma unroll
        for (int nb = 0; nb < 8; nb++) {
            const int col = bn0 + wn * 64 + nb * 8 + 2 * tig;
            float c0 = acc[mi][nb][0] * oscale, c1 = acc[mi][nb][1] * oscale;
            float c2 = acc[mi][nb][2] * oscale, c3 = acc[mi][nb][3] * oscale;
            if (BIAS) {
                const float b0 = bias[col], b1 = bias[col + 1];
                c0 += b0; c1 += b1; c2 += b0; c3 += b1;
            }
            if (HALF_OUT) {
                __half* C = (__half*)Cv;
                *reinterpret_cast<uint32_t*>(&C[(size_t)row0 * N + col])       = pack2(c0, c1);
                *reinterpret_cast<uint32_t*>(&C[(size_t)(row0 + 8) * N + col]) = pack2(c2, c3);
            } else {
                float* C = (float*)Cv;
                *reinterpret_cast<float2*>(&C[(size_t)row0 * N + col])       = make_float2(c0, c1);
                *reinterpret_cast<float2*>(&C[(size_t)(row0 + 8) * N + col]) = make_float2(c2, c3);
            }
        }
    }
}

// ---------------------------------------------------------------------------
// fp16 flash attention v11: SPLIT-KV x4 on persistent-444.
//  Unnormalized softmax (p = ex2(s)) makes partial O and row-sums additive
//  across disjoint KV ranges -> each quarter-unit (512 kv rows, NT=4 tiles of
//  128) writes fp32 unnormalized O partials + row-sum partials. 2048 units on
//  444 slots: makespan 5 quarter-rounds = 1.25 unit-times (92% efficiency)
//  vs 2.0 (58%). reduce4 kernel sums/normalizes -> fp16 A.
// ---------------------------------------------------------------------------
constexpr int ALD = 72;
constexpr int AKV = 128;
constexpr int ATILE = AKV * ALD;
constexpr int ATT_SMEM = 2 * 2 * ATILE * 2;   // 73728 B
constexpr int NKV_PER = NKV / ASPLIT;         // 512
constexpr int AUNITS = (NQ / 128) * HEADS * B_ * ASPLIT;  // 2048
constexpr int AGRID  = 148 * 3;                           // 444

__global__ __launch_bounds__(128, 3)
void attn11(const __half* __restrict__ Q, const __half* __restrict__ K,
            const __half* __restrict__ V, float* __restrict__ OP,
            float* __restrict__ SUM) {
    extern __shared__ __half sh[];

    const int tid  = threadIdx.x;
    const int w    = tid >> 5;
    const int lane = tid & 31;
    const int g    = lane >> 2;
    const int tig  = lane & 3;
    const int lmr = lane & 15;
    const int lmc = (lane >> 4) * 8;

    // ones-pad init: V tiles' cols 64-71 = [1,0,...] in both buffers
#pragma unroll
    for (int i = 0; i < 2; i++) {
        const int idx = tid + i * 128;
        const int buf = idx >> 7, r = idx & 127;
        uint4 ones = make_uint4(0x00003C00u, 0u, 0u, 0u);
        *reinterpret_cast<uint4*>(sh + (buf * 2 + 1) * ATILE + r * ALD + 64) = ones;
    }

    auto prefetch = [&](const __half* Kg, const __half* Vg, int buf, int j0) {
#pragma unroll
        for (int i = 0; i < 8; i++) {
            const int idx = tid + i * 128;
            const int r = idx >> 3, c = idx & 7;
            cp_async16(&sh[buf * 2 * ATILE + r * ALD + c * 8],
                       Kg + (size_t)(j0 + r) * INNER + c * 8);
        }
#pragma unroll
        for (int i = 0; i < 8; i++) {
            const int idx = tid + i * 128;
            const int r = idx >> 3, c = idx & 7;
            cp_async16(&sh[buf * 2 * ATILE + ATILE + r * ALD + c * 8],
                       Vg + (size_t)(j0 + r) * INNER + c * 8);
        }
    };

    for (int u = blockIdx.x; u < AUNITS; u += AGRID) {
        const int s    = u & (ASPLIT - 1);
        const int unit = u >> 2;
        const int qt = unit & 15;
        const int hb = unit >> 4;
        const int h  = hb & 15;
        const int b  = hb >> 4;
        const int q0 = qt * 128;
        const int kv0 = s * NKV_PER;

        const __half* Kg = K + (size_t)(b * NKV) * INNER + h * DIMH;
        const __half* Vg = V + (size_t)(b * NKV) * INNER + h * DIMH;

        // issue first K/V tile load BEFORE Q frag loads (overlap)
        prefetch(Kg, Vg, 0, kv0);
        cp_commit();

        uint32_t qa0[4][4], qa1[4][4];
        const int r0 = q0 + w * 32 + g;
        {
            const __half* Q0 = Q + (size_t)(b * NQ + r0) * INNER + h * DIMH;
            const __half* Q1 = Q0 + 8 * (size_t)INNER;
            const __half* Q2 = Q0 + 16 * (size_t)INNER;
            const __half* Q3 = Q0 + 24 * (size_t)INNER;
#pragma unroll
            for (int kk = 0; kk < 4; kk++) {
                qa0[kk][0] = *reinterpret_cast<const uint32_t*>(Q0 + kk * 16 + 2 * tig);
                qa0[kk][1] = *reinterpret_cast<const uint32_t*>(Q1 + kk * 16 + 2 * tig);
                qa0[kk][2] = *reinterpret_cast<const uint32_t*>(Q0 + kk * 16 + 2 * tig + 8);
                qa0[kk][3] = *reinterpret_cast<const uint32_t*>(Q1 + kk * 16 + 2 * tig + 8);
                qa1[kk][0] = *reinterpret_cast<const uint32_t*>(Q2 + kk * 16 + 2 * tig);
                qa1[kk][1] = *reinterpret_cast<const uint32_t*>(Q3 + kk * 16 + 2 * tig);
                qa1[kk][2] = *reinterpret_cast<const uint32_t*>(Q2 + kk * 16 + 2 * tig + 8);
                qa1[kk][3] = *reinterpret_cast<const uint32_t*>(Q3 + kk * 16 + 2 * tig + 8);
            }
        }

        float oa0[8][4], oa1[8][4];
        float sum0[4] = {0.f, 0.f, 0.f, 0.f};
        float sum1[4] = {0.f, 0.f, 0.f, 0.f};
#pragma unroll
        for (int nb = 0; nb < 8; nb++)
#pragma unroll
            for (int e = 0; e < 4; e++) { oa0[nb][e] = 0.0f; oa1[nb][e] = 0.0f; }

        constexpr int NT = NKV_PER / AKV;   // 4
        for (int t = 0; t < NT; t++) {
            const int buf = t & 1;
            asm volatile("cp.async.wait_group 0;\n");
            __syncthreads();
            if (t + 1 < NT) { prefetch(Kg, Vg, buf ^ 1, kv0 + (t + 1) * AKV); cp_commit(); }

            const __half* Kb = sh + buf * 2 * ATILE;
            const __half* Vb = Kb + ATILE;

#pragma unroll
            for (int nbp = 0; nbp < 8; nbp++) {
                float s00[4] = {0.f,0.f,0.f,0.f}, s01[4] = {0.f,0.f,0.f,0.f};
                float s10[4] = {0.f,0.f,0.f,0.f}, s11[4] = {0.f,0.f,0.f,0.f};
#pragma unroll
                for (int kk = 0; kk < 4; kk++) {
                    uint32_t b0, b1, b2, b3;
                    ldmx4(b0, b1, b2, b3, Kb + (nbp * 16 + lmr) * ALD + kk * 16 + lmc);
                    mma_f16(s00, qa0[kk], b0, b2);
                    mma_f16(s01, qa0[kk], b1, b3);
                    mma_f16(s10, qa1[kk], b0, b2);
                    mma_f16(s11, qa1[kk], b1, b3);
                }
                uint32_t pa0[4], pa1[4];
                pa0[0] = pack2(ex2(s00[0]), ex2(s00[1]));
                pa0[1] = pack2(ex2(s00[2]), ex2(s00[3]));
                pa0[2] = pack2(ex2(s01[0]), ex2(s01[1]));
                pa0[3] = pack2(ex2(s01[2]), ex2(s01[3]));
                pa1[0] = pack2(ex2(s10[0]), ex2(s10[1]));
                pa1[1] = pack2(ex2(s10[2]), ex2(s10[3]));
                pa1[2] = pack2(ex2(s11[0]), ex2(s11[1]));
                pa1[3] = pack2(ex2(s11[2]), ex2(s11[3]));

#pragma unroll
                for (int j = 0; j < 4; j++) {
                    uint32_t b0, b1, b2, b3;
                    ldmx4_trans(b0, b1, b2, b3, Vb + (nbp * 16 + lmr) * ALD + j * 16 + lmc);
                    mma_f16(oa0[2 * j],     pa0, b0, b1);
                    mma_f16(oa0[2 * j + 1], pa0, b2, b3);
                    mma_f16(oa1[2 * j],     pa1, b0, b1);
                    mma_f16(oa1[2 * j + 1], pa1, b2, b3);
                }
                {
                    uint32_t c0, c1;
                    ldmx2_trans(c0, c1, Vb + (nbp * 16 + lmr) * ALD + 64);
                    mma_f16(sum0, pa0, c0, c1);
                    mma_f16(sum1, pa1, c0, c1);
                }
            }
        }

        // write unnormalized fp32 partials (split s)
        float* P0 = OP + ((size_t)s * ROWS + b * NQ + r0) * INNER + h * DIMH;
        float* P1 = P0 + 8 * (size_t)INNER;
        float* P2 = P0 + 16 * (size_t)INNER;
        float* P3 = P0 + 24 * (size_t)INNER;
#pragma unroll
        for (int nb = 0; nb < 8; nb++) {
            *reinterpret_cast<float2*>(P0 + nb * 8 + 2 * tig) = make_float2(oa0[nb][0], oa0[nb][1]);
            *reinterpret_cast<float2*>(P1 + nb * 8 + 2 * tig) = make_float2(oa0[nb][2], oa0[nb][3]);
            *reinterpret_cast<float2*>(P2 + nb * 8 + 2 * tig) = make_float2(oa1[nb][0], oa1[nb][1]);
            *reinterpret_cast<float2*>(P3 + nb * 8 + 2 * tig) = make_float2(oa1[nb][2], oa1[nb][3]);
        }
        // row-sum partials live in tig==0 lanes: sum0[0]=row g, sum0[2]=row g+8,
        // sum1[0]=row g+16, sum1[2]=row g+24
        if (tig == 0) {
            float* S0 = SUM + ((size_t)s * ROWS + b * NQ + r0) * HEADS + h;
            S0[0]          = sum0[0];
            S0[8  * HEADS] = sum0[2];
            S0[16 * HEADS] = sum1[0];
            S0[24 * HEADS] = sum1[2];
        }
    }
}

// ---------------------------------------------------------------------------
// reduce: A[gr, col] = fp16( sum_s OP[s][gr][col] / sum_s SUM[s][gr][h] )
// ---------------------------------------------------------------------------
__global__ void reduce4(__half* __restrict__ A, const float* __restrict__ OP,
                        const float* __restrict__ SUM) {
    const int i = blockIdx.x * blockDim.x + threadIdx.x;   // float4 index
    const int gr = i >> 8;            // 256 float4 per row (INNER/4)
    const int c4 = i & 255;
    const int h  = c4 >> 4;           // (c4*4)/64
    float4 acc = make_float4(0.f, 0.f, 0.f, 0.f);
    float ssum = 0.f;
#pragma unroll
    for (int s = 0; s < ASPLIT; s++) {
        const float4 v = *reinterpret_cast<const float4*>(
            OP + ((size_t)s * ROWS + gr) * INNER + c4 * 4);
        acc.x += v.x; acc.y += v.y; acc.z += v.z; acc.w += v.w;
        ssum += SUM[((size_t)s * ROWS + gr) * HEADS + h];
    }
    const float inv = 1.0f / ssum;
    uint2 o;
    o.x = pack2(acc.x * inv, acc.y * inv);
    o.y = pack2(acc.z * inv, acc.w * inv);
    *reinterpret_cast<uint2*>(A + (size_t)gr * INNER + c4 * 4) = o;
}

// ---------------------------------------------------------------------------
extern "C" void kernel_launch(void* const* d_in, const int* in_sizes, int n_in,
                              void* d_out, int out_size) {
    const float* patch = (const float*)d_in[0];
    const float* pixel = (const float*)d_in[1];
    const float* Wq    = (const float*)d_in[2];
    const float* Wk    = (const float*)d_in[3];
    const float* Wv    = (const float*)d_in[4];
    const float* Wo    = (const float*)d_in[5];
    const float* bo    = (const float*)d_in[6];
    float* out = (float*)d_out;

    __half *pQ, *pK, *pV, *pA, *pPA, *pPX, *pWQ, *pWK, *pWV, *pWO;
    float *pOP, *pSUM;
    cudaGetSymbolAddress((void**)&pQ,  g_Q);
    cudaGetSymbolAddress((void**)&pK,  g_K);
    cudaGetSymbolAddress((void**)&pV,  g_V);
    cudaGetSymbolAddress((void**)&pA,  g_A);
    cudaGetSymbolAddress((void**)&pPA, g_PA);
    cudaGetSymbolAddress((void**)&pPX, g_PX);
    cudaGetSymbolAddress((void**)&pWQ, g_WQ);
    cudaGetSymbolAddress((void**)&pWK, g_WK);
    cudaGetSymbolAddress((void**)&pWV, g_WV);
    cudaGetSymbolAddress((void**)&pWO, g_WO);
    cudaGetSymbolAddress((void**)&pOP,  g_OP);
    cudaGetSymbolAddress((void**)&pSUM, g_SUM);

    cudaFuncSetAttribute((const void*)hgemm<true, true, false>,
                         cudaFuncAttributeMaxDynamicSharedMemorySize, HG_SMEM);
    cudaFuncSetAttribute((const void*)hgemm<false, false, true>,
                         cudaFuncAttributeMaxDynamicSharedMemorySize, HG_SMEM);
    cudaFuncSetAttribute(attn11, cudaFuncAttributeMaxDynamicSharedMemorySize, ATT_SMEM);

    // 1) prep: activations -> fp16 (MLP=4); weight transposes (merged)
    const int actN4 = ROWS * D / 4;              // 1048576
    const int cvblocks = actN4 / (4 * 256);      // 1024
    cvth4<<<dim3(cvblocks, 2), 256>>>(pPA, (const float4*)patch,
                                      pPX, (const float4*)pixel,
                                      actN4, cvblocks * 256);
    transpose_cvt4<<<dim3(32, 32, 4), dim3(32, 8)>>>(pWQ, Wq, pWK, Wk, pWV, Wv, pWO, Wo);

    // 2) Q/K/V projections (one launch); Q scaled by scale*log2e
    dim3 ggrid(INNER / 128, ROWS / 128, 3);
    hgemm<true, true, false><<<ggrid, 256, HG_SMEM>>>(
        pPA, pWQ, pQ, pPX, pWK, pK, pPX, pWV, pV, nullptr, ROWS, INNER, D, SCALE_LOG2E);

    // 3) attention (split-KV x4, persistent-444) + reduce/normalize
    attn11<<<AGRID, 128, ATT_SMEM>>>(pQ, pK, pV, pOP, pSUM);
    reduce4<<<ROWS * INNER / 4 / 256, 256>>>(pA, pOP, pSUM);

    // 4) output projection + bias (fp32 out)
    dim3 ogrid(D / 128, ROWS / 128, 1);
    hgemm<false, false, true><<<ogrid, 256, HG_SMEM>>>(
        pA, pWO, out, nullptr, nullptr, nullptr, nullptr, nullptr, nullptr,
        bo, ROWS, D, INNER, 1.0f);
}

// round 17
// speedup vs baseline: 1.0944x; 1.0944x over previous
#include <cuda_runtime.h>
#include <cuda_fp16.h>
#include <math.h>
#include <stdint.h>

constexpr int B_    = 2;
constexpr int NQ    = 2048;
constexpr int NKV   = 2048;
constexpr int D     = 1024;
constexpr int INNER = 1024;
constexpr int HEADS = 16;
constexpr int DIMH  = 64;

constexpr int ROWS = B_ * NQ; // 4096
constexpr float SCALE_LOG2E = 0.125f * 1.4426950408889634f;

// Scratch (allocation-free rule: __device__ globals)
__device__ __half g_Q[ROWS * INNER];
__device__ __half g_K[ROWS * INNER];
__device__ __half g_V[ROWS * INNER];
__device__ __half g_A[ROWS * INNER];
__device__ __half g_PA[ROWS * D];
__device__ __half g_PX[ROWS * D];
__device__ __half g_WQ[D * INNER];   // transposed weights [N][K]
__device__ __half g_WK[D * INNER];
__device__ __half g_WV[D * INNER];
__device__ __half g_WO[INNER * D];

// ---------------------------------------------------------------------------
// helpers
// ---------------------------------------------------------------------------
__device__ __forceinline__ void cp_async16(void* dst, const void* src) {
    uint32_t s = (uint32_t)__cvta_generic_to_shared(dst);
    asm volatile("cp.async.cg.shared.global [%0], [%1], 16;\n" :: "r"(s), "l"(src));
}
__device__ __forceinline__ void cp_commit() { asm volatile("cp.async.commit_group;\n"); }

__device__ __forceinline__ float ex2(float x) {
    float r; asm("ex2.approx.ftz.f32 %0, %1;" : "=f"(r) : "f"(x)); return r;
}
__device__ __forceinline__ uint32_t pack2(float lo, float hi) {
    uint32_t r;
    asm("cvt.rn.f16x2.f32 %0, %1, %2;" : "=r"(r) : "f"(hi), "f"(lo));
    return r;
}

__device__ __forceinline__ void mma_f16(float* c, const uint32_t* a, uint32_t b0, uint32_t b1) {
    asm volatile(
        "mma.sync.aligned.m16n8k16.row.col.f32.f16.f16.f32 "
        "{%0,%1,%2,%3}, {%4,%5,%6,%7}, {%8,%9}, {%0,%1,%2,%3};\n"
        : "+f"(c[0]), "+f"(c[1]), "+f"(c[2]), "+f"(c[3])
        : "r"(a[0]), "r"(a[1]), "r"(a[2]), "r"(a[3]), "r"(b0), "r"(b1));
}

__device__ __forceinline__ void ldmx4(uint32_t& r0, uint32_t& r1, uint32_t& r2, uint32_t& r3,
                                      const void* p) {
    uint32_t a = (uint32_t)__cvta_generic_to_shared(p);
    asm volatile("ldmatrix.sync.aligned.m8n8.x4.shared.b16 {%0,%1,%2,%3}, [%4];"
                 : "=r"(r0), "=r"(r1), "=r"(r2), "=r"(r3) : "r"(a));
}
__device__ __forceinline__ void ldmx4_trans(uint32_t& r0, uint32_t& r1, uint32_t& r2, uint32_t& r3,
                                            const void* p) {
    uint32_t a = (uint32_t)__cvta_generic_to_shared(p);
    asm volatile("ldmatrix.sync.aligned.m8n8.x4.trans.shared.b16 {%0,%1,%2,%3}, [%4];"
                 : "=r"(r0), "=r"(r1), "=r"(r2), "=r"(r3) : "r"(a));
}
__device__ __forceinline__ void ldmx2_trans(uint32_t& r0, uint32_t& r1, const void* p) {
    uint32_t a = (uint32_t)__cvta_generic_to_shared(p);
    asm volatile("ldmatrix.sync.aligned.m8n8.x2.trans.shared.b16 {%0,%1}, [%2];"
                 : "=r"(r0), "=r"(r1) : "r"(a));
}

// ---------------------------------------------------------------------------
// prep kernels
// ---------------------------------------------------------------------------
__global__ void cvth4(__half* __restrict__ d0, const float4* __restrict__ s0,
                      __half* __restrict__ d1, const float4* __restrict__ s1,
                      int n4, int stride) {
    const int base = blockIdx.x * blockDim.x + threadIdx.x;
    const float4* s = blockIdx.y ? s1 : s0;
    __half* d = blockIdx.y ? d1 : d0;
    float4 v[4];
#pragma unroll
    for (int k = 0; k < 4; k++) {
        const int i = base + k * stride;
        v[k] = s[i];
    }
#pragma unroll
    for (int k = 0; k < 4; k++) {
        const int i = base + k * stride;
        uint2 o;
        o.x = pack2(v[k].x, v[k].y);
        o.y = pack2(v[k].z, v[k].w);
        *reinterpret_cast<uint2*>(d + 4 * (size_t)i) = o;
    }
}

__global__ void transpose_cvt4(__half* __restrict__ d0, const float* __restrict__ s0,
                               __half* __restrict__ d1, const float* __restrict__ s1,
                               __half* __restrict__ d2, const float* __restrict__ s2,
                               __half* __restrict__ d3, const float* __restrict__ s3) {
    __shared__ float t[32][33];
    const int z = blockIdx.z;
    const float* src = (z == 0) ? s0 : (z == 1) ? s1 : (z == 2) ? s2 : s3;
    __half* dst = (z == 0) ? d0 : (z == 1) ? d1 : (z == 2) ? d2 : d3;
    const int n0 = blockIdx.x * 32;
    const int k0 = blockIdx.y * 32;
    const int tx = threadIdx.x, ty = threadIdx.y;
#pragma unroll
    for (int i = 0; i < 4; i++)
        t[ty + i * 8][tx] = src[(size_t)(k0 + ty + i * 8) * 1024 + n0 + tx];
    __syncthreads();
#pragma unroll
    for (int i = 0; i < 4; i++)
        dst[(size_t)(n0 + ty + i * 8) * 1024 + k0 + tx] = __float2half_rn(t[tx][ty + i * 8]);
}

// ---------------------------------------------------------------------------
// fp16 GEMM v3: BM=BN=128, BK=64 (16 iters, syncs halved vs BK=32),
// 3-stage cp.async, 256 thr, 8 warps 4x2, warp tile 32x64, 2 blocks/SM.
// Row stride 72 halves (144B) -- ldmatrix conflict-free (same as attention).
// ---------------------------------------------------------------------------
constexpr int HG_LD = 72;                        // halves per row (64 + 8 pad)
constexpr int HG_TILE = 128 * HG_LD;             // halves per A or B tile
constexpr int HG_STAGE = 2 * HG_TILE;            // A + B
constexpr int HG_STAGES = 3;
constexpr int HG_SMEM = HG_STAGES * HG_STAGE * 2; // 110592 B

template <bool QKV, bool HALF_OUT, bool BIAS>
__global__ __launch_bounds__(256, 2)
void hgemm3(const __half* __restrict__ A0, const __half* __restrict__ W0, void* __restrict__ C0,
            const __half* __restrict__ A1, const __half* __restrict__ W1, void* __restrict__ C1,
            const __half* __restrict__ A2, const __half* __restrict__ W2, void* __restrict__ C2,
            const float* __restrict__ bias, int M, int N, int K, float oscale0) {
    extern __shared__ __half sh[];

    const __half* A = A0; const __half* WT = W0; void* Cv = C0;
    float oscale = oscale0;
    if (QKV) {
        const int z = blockIdx.z;
        if (z == 1) { A = A1; WT = W1; Cv = C1; oscale = 1.0f; }
        else if (z == 2) { A = A2; WT = W2; Cv = C2; oscale = 1.0f; }
    }

    const int tid  = threadIdx.x;
    const int wid  = tid >> 5;
    const int lane = tid & 31;
    const int g    = lane >> 2;
    const int tig  = lane & 3;
    const int wm = wid >> 1;
    const int wn = wid & 1;
    const int bm0 = blockIdx.y * 128;
    const int bn0 = blockIdx.x * 128;
    const int lmr = lane & 15;
    const int lmc = (lane >> 4) * 8;

    float acc[2][8][4];
#pragma unroll
    for (int mi = 0; mi < 2; mi++)
#pragma unroll
        for (int nb = 0; nb < 8; nb++)
#pragma unroll
            for (int e = 0; e < 4; e++) acc[mi][nb][e] = 0.0f;

    auto load_tiles = [&](int buf, int k0) {
        __half* As = sh + buf * HG_STAGE;
        __half* Bs = As + HG_TILE;
        // A: 128 rows x 8 chunks (128B/row) = 1024 chunks / 256 thr = 4 each
#pragma unroll
        for (int i = 0; i < 4; i++) {
            const int idx = tid + i * 256;
            const int r = idx >> 3, c = idx & 7;
            cp_async16(&As[r * HG_LD + c * 8],
                       &A[(size_t)(bm0 + r) * K + k0 + c * 8]);
        }
#pragma unroll
        for (int i = 0; i < 4; i++) {
            const int idx = tid + i * 256;
            const int r = idx >> 3, c = idx & 7;
            cp_async16(&Bs[r * HG_LD + c * 8],
                       &WT[(size_t)(bn0 + r) * K + k0 + c * 8]);
        }
    };

    const int KT = K / 64;    // 16
    load_tiles(0, 0);  cp_commit();
    load_tiles(1, 64); cp_commit();

    for (int t = 0; t < KT; t++) {
        const int buf = t % 3;
        asm volatile("cp.async.wait_group 1;\n");
        __syncthreads();
        if (t + 2 < KT) { load_tiles((t + 2) % 3, (t + 2) * 64); cp_commit(); }

        const __half* Ab = sh + buf * HG_STAGE;
        const __half* Bb = Ab + HG_TILE;
#pragma unroll
        for (int ks = 0; ks < 4; ks++) {
            uint32_t a[2][4];
            uint32_t b[4][4];
#pragma unroll
            for (int mi = 0; mi < 2; mi++)
                ldmx4(a[mi][0], a[mi][1], a[mi][2], a[mi][3],
                      Ab + (wm * 32 + mi * 16 + lmr) * HG_LD + ks * 16 + lmc);
#pragma unroll
            for (int nbp = 0; nbp < 4; nbp++)
                ldmx4(b[nbp][0], b[nbp][1], b[nbp][2], b[nbp][3],
                      Bb + (wn * 64 + nbp * 16 + lmr) * HG_LD + ks * 16 + lmc);
#pragma unroll
            for (int nbp = 0; nbp < 4; nbp++)
#pragma unroll
                for (int mi = 0; mi < 2; mi++) {
                    mma_f16(acc[mi][2 * nbp],     a[mi], b[nbp][0], b[nbp][2]);
                    mma_f16(acc[mi][2 * nbp + 1], a[mi], b[nbp][1], b[nbp][3]);
                }
        }
    }

#pragma unroll
    for (int mi = 0; mi < 2; mi++) {
        const int row0 = bm0 + wm * 32 + mi * 16 + g;
#pragma unroll
        for (int nb = 0; nb < 8; nb++) {
            const int col = bn0 + wn * 64 + nb * 8 + 2 * tig;
            float c0 = acc[mi][nb][0] * oscale, c1 = acc[mi][nb][1] * oscale;
            float c2 = acc[mi][nb][2] * oscale, c3 = acc[mi][nb][3] * oscale;
            if (BIAS) {
                const float b0 = bias[col], b1 = bias[col + 1];
                c0 += b0; c1 += b1; c2 += b0; c3 += b1;
            }
            if (HALF_OUT) {
                __half* C = (__half*)Cv;
                *reinterpret_cast<uint32_t*>(&C[(size_t)row0 * N + col])       = pack2(c0, c1);
                *reinterpret_cast<uint32_t*>(&C[(size_t)(row0 + 8) * N + col]) = pack2(c2, c3);
            } else {
                float* C = (float*)Cv;
                *reinterpret_cast<float2*>(&C[(size_t)row0 * N + col])       = make_float2(c0, c1);
                *reinterpret_cast<float2*>(&C[(size_t)(row0 + 8) * N + col]) = make_float2(c2, c3);
            }
        }
    }
}

// ---------------------------------------------------------------------------
// fp16 flash attention (attn10, round-15 best: 101.2us): persistent-444,
// 4 warps x 32 q-rows, kv-tile 128, unnormalized fp32 ex2 softmax,
// ones-column mma row sums. UNCHANGED.
// ---------------------------------------------------------------------------
constexpr int ALD = 72;
constexpr int AKV = 128;
constexpr int ATILE = AKV * ALD;
constexpr int ATT_SMEM = 2 * 2 * ATILE * 2;   // 73728 B
constexpr int AUNITS = (NQ / 128) * HEADS * B_;  // 512
constexpr int AGRID  = 148 * 3;                   // 444

__global__ __launch_bounds__(128, 3)
void attn10(const __half* __restrict__ Q, const __half* __restrict__ K,
            const __half* __restrict__ V, __half* __restrict__ O) {
    extern __shared__ __half sh[];

    const int tid  = threadIdx.x;
    const int w    = tid >> 5;
    const int lane = tid & 31;
    const int g    = lane >> 2;
    const int tig  = lane & 3;
    const int lmr = lane & 15;
    const int lmc = (lane >> 4) * 8;

#pragma unroll
    for (int i = 0; i < 2; i++) {
        const int idx = tid + i * 128;
        const int buf = idx >> 7, r = idx & 127;
        uint4 ones = make_uint4(0x00003C00u, 0u, 0u, 0u);
        *reinterpret_cast<uint4*>(sh + (buf * 2 + 1) * ATILE + r * ALD + 64) = ones;
    }

    auto prefetch = [&](const __half* Kg, const __half* Vg, int buf, int j0) {
#pragma unroll
        for (int i = 0; i < 8; i++) {
            const int idx = tid + i * 128;
            const int r = idx >> 3, c = idx & 7;
            cp_async16(&sh[buf * 2 * ATILE + r * ALD + c * 8],
                       Kg + (size_t)(j0 + r) * INNER + c * 8);
        }
#pragma unroll
        for (int i = 0; i < 8; i++) {
            const int idx = tid + i * 128;
            const int r = idx >> 3, c = idx & 7;
            cp_async16(&sh[buf * 2 * ATILE + ATILE + r * ALD + c * 8],
                       Vg + (size_t)(j0 + r) * INNER + c * 8);
        }
    };

    for (int u = blockIdx.x; u < AUNITS; u += AGRID) {
        const int qt = u & 15;
        const int hb = u >> 4;
        const int h  = hb & 15;
        const int b  = hb >> 4;
        const int q0 = qt * 128;

        const __half* Kg = K + (size_t)(b * NKV) * INNER + h * DIMH;
        const __half* Vg = V + (size_t)(b * NKV) * INNER + h * DIMH;

        uint32_t qa0[4][4], qa1[4][4];
        const int r0 = q0 + w * 32 + g;
        {
            const __half* Q0 = Q + (size_t)(b * NQ + r0) * INNER + h * DIMH;
            const __half* Q1 = Q0 + 8 * (size_t)INNER;
            const __half* Q2 = Q0 + 16 * (size_t)INNER;
            const __half* Q3 = Q0 + 24 * (size_t)INNER;
#pragma unroll
            for (int kk = 0; kk < 4; kk++) {
                qa0[kk][0] = *reinterpret_cast<const uint32_t*>(Q0 + kk * 16 + 2 * tig);
                qa0[kk][1] = *reinterpret_cast<const uint32_t*>(Q1 + kk * 16 + 2 * tig);
                qa0[kk][2] = *reinterpret_cast<const uint32_t*>(Q0 + kk * 16 + 2 * tig + 8);
                qa0[kk][3] = *reinterpret_cast<const uint32_t*>(Q1 + kk * 16 + 2 * tig + 8);
                qa1[kk][0] = *reinterpret_cast<const uint32_t*>(Q2 + kk * 16 + 2 * tig);
                qa1[kk][1] = *reinterpret_cast<const uint32_t*>(Q3 + kk * 16 + 2 * tig);
                qa1[kk][2] = *reinterpret_cast<const uint32_t*>(Q2 + kk * 16 + 2 * tig + 8);
                qa1[kk][3] = *reinterpret_cast<const uint32_t*>(Q3 + kk * 16 + 2 * tig + 8);
            }
        }

        float oa0[8][4], oa1[8][4];
        float sum0[4] = {0.f, 0.f, 0.f, 0.f};
        float sum1[4] = {0.f, 0.f, 0.f, 0.f};
#pragma unroll
        for (int nb = 0; nb < 8; nb++)
#pragma unroll
            for (int e = 0; e < 4; e++) { oa0[nb][e] = 0.0f; oa1[nb][e] = 0.0f; }

        prefetch(Kg, Vg, 0, 0);
        cp_commit();

        constexpr int NT = NKV / AKV;   // 16
        for (int t = 0; t < NT; t++) {
            const int buf = t & 1;
            asm volatile("cp.async.wait_group 0;\n");
            __syncthreads();
            if (t + 1 < NT) { prefetch(Kg, Vg, buf ^ 1, (t + 1) * AKV); cp_commit(); }

            const __half* Kb = sh + buf * 2 * ATILE;
            const __half* Vb = Kb + ATILE;

#pragma unroll
            for (int nbp = 0; nbp < 8; nbp++) {
                float s00[4] = {0.f,0.f,0.f,0.f}, s01[4] = {0.f,0.f,0.f,0.f};
                float s10[4] = {0.f,0.f,0.f,0.f}, s11[4] = {0.f,0.f,0.f,0.f};
#pragma unroll
                for (int kk = 0; kk < 4; kk++) {
                    uint32_t b0, b1, b2, b3;
                    ldmx4(b0, b1, b2, b3, Kb + (nbp * 16 + lmr) * ALD + kk * 16 + lmc);
                    mma_f16(s00, qa0[kk], b0, b2);
                    mma_f16(s01, qa0[kk], b1, b3);
                    mma_f16(s10, qa1[kk], b0, b2);
                    mma_f16(s11, qa1[kk], b1, b3);
                }
                uint32_t pa0[4], pa1[4];
                pa0[0] = pack2(ex2(s00[0]), ex2(s00[1]));
                pa0[1] = pack2(ex2(s00[2]), ex2(s00[3]));
                pa0[2] = pack2(ex2(s01[0]), ex2(s01[1]));
                pa0[3] = pack2(ex2(s01[2]), ex2(s01[3]));
                pa1[0] = pack2(ex2(s10[0]), ex2(s10[1]));
                pa1[1] = pack2(ex2(s10[2]), ex2(s10[3]));
                pa1[2] = pack2(ex2(s11[0]), ex2(s11[1]));
                pa1[3] = pack2(ex2(s11[2]), ex2(s11[3]));

#pragma unroll
                for (int j = 0; j < 4; j++) {
                    uint32_t b0, b1, b2, b3;
                    ldmx4_trans(b0, b1, b2, b3, Vb + (nbp * 16 + lmr) * ALD + j * 16 + lmc);
                    mma_f16(oa0[2 * j],     pa0, b0, b1);
                    mma_f16(oa0[2 * j + 1], pa0, b2, b3);
                    mma_f16(oa1[2 * j],     pa1, b0, b1);
                    mma_f16(oa1[2 * j + 1], pa1, b2, b3);
                }
                {
                    uint32_t c0, c1;
                    ldmx2_trans(c0, c1, Vb + (nbp * 16 + lmr) * ALD + 64);
                    mma_f16(sum0, pa0, c0, c1);
                    mma_f16(sum1, pa1, c0, c1);
                }
            }
        }

        const int src = lane & 28;
        const float inv00 = 1.0f / __shfl_sync(0xffffffffu, sum0[0], src);
        const float inv01 = 1.0f / __shfl_sync(0xffffffffu, sum0[2], src);
        const float inv10 = 1.0f / __shfl_sync(0xffffffffu, sum1[0], src);
        const float inv11 = 1.0f / __shfl_sync(0xffffffffu, sum1[2], src);

        __half* O0 = O + (size_t)(b * NQ + r0) * INNER + h * DIMH;
        __half* O1 = O0 + 8 * (size_t)INNER;
        __half* O2 = O0 + 16 * (size_t)INNER;
        __half* O3 = O0 + 24 * (size_t)INNER;
#pragma unroll
        for (int nb = 0; nb < 8; nb++) {
            *reinterpret_cast<uint32_t*>(O0 + nb * 8 + 2 * tig) =
                pack2(oa0[nb][0] * inv00, oa0[nb][1] * inv00);
            *reinterpret_cast<uint32_t*>(O1 + nb * 8 + 2 * tig) =
                pack2(oa0[nb][2] * inv01, oa0[nb][3] * inv01);
            *reinterpret_cast<uint32_t*>(O2 + nb * 8 + 2 * tig) =
                pack2(oa1[nb][0] * inv10, oa1[nb][1] * inv10);
            *reinterpret_cast<uint32_t*>(O3 + nb * 8 + 2 * tig) =
                pack2(oa1[nb][2] * inv11, oa1[nb][3] * inv11);
        }
    }
}

// ---------------------------------------------------------------------------
extern "C" void kernel_launch(void* const* d_in, const int* in_sizes, int n_in,
                              void* d_out, int out_size) {
    const float* patch = (const float*)d_in[0];
    const float* pixel = (const float*)d_in[1];
    const float* Wq    = (const float*)d_in[2];
    const float* Wk    = (const float*)d_in[3];
    const float* Wv    = (const float*)d_in[4];
    const float* Wo    = (const float*)d_in[5];
    const float* bo    = (const float*)d_in[6];
    float* out = (float*)d_out;

    __half *pQ, *pK, *pV, *pA, *pPA, *pPX, *pWQ, *pWK, *pWV, *pWO;
    cudaGetSymbolAddress((void**)&pQ,  g_Q);
    cudaGetSymbolAddress((void**)&pK,  g_K);
    cudaGetSymbolAddress((void**)&pV,  g_V);
    cudaGetSymbolAddress((void**)&pA,  g_A);
    cudaGetSymbolAddress((void**)&pPA, g_PA);
    cudaGetSymbolAddress((void**)&pPX, g_PX);
    cudaGetSymbolAddress((void**)&pWQ, g_WQ);
    cudaGetSymbolAddress((void**)&pWK, g_WK);
    cudaGetSymbolAddress((void**)&pWV, g_WV);
    cudaGetSymbolAddress((void**)&pWO, g_WO);

    cudaFuncSetAttribute((const void*)hgemm3<true, true, false>,
                         cudaFuncAttributeMaxDynamicSharedMemorySize, HG_SMEM);
    cudaFuncSetAttribute((const void*)hgemm3<false, false, true>,
                         cudaFuncAttributeMaxDynamicSharedMemorySize, HG_SMEM);
    cudaFuncSetAttribute(attn10, cudaFuncAttributeMaxDynamicSharedMemorySize, ATT_SMEM);

    // 1) prep: activations -> fp16 (MLP=4); weight transposes (merged)
    const int actN4 = ROWS * D / 4;              // 1048576
    const int cvblocks = actN4 / (4 * 256);      // 1024
    cvth4<<<dim3(cvblocks, 2), 256>>>(pPA, (const float4*)patch,
                                      pPX, (const float4*)pixel,
                                      actN4, cvblocks * 256);
    transpose_cvt4<<<dim3(32, 32, 4), dim3(32, 8)>>>(pWQ, Wq, pWK, Wk, pWV, Wv, pWO, Wo);

    // 2) Q/K/V projections (one launch); Q scaled by scale*log2e
    dim3 ggrid(INNER / 128, ROWS / 128, 3);      // (8, 32, 3) = 768 blocks
    hgemm3<true, true, false><<<ggrid, 256, HG_SMEM>>>(
        pPA, pWQ, pQ, pPX, pWK, pK, pPX, pWV, pV, nullptr, ROWS, INNER, D, SCALE_LOG2E);

    // 3) attention (persistent-444, kv-tile 128 -- round-15 best)
    attn10<<<AGRID, 128, ATT_SMEM>>>(pQ, pK, pV, pA);

    // 4) output projection + bias (fp32 out)
    dim3 ogrid(D / 128, ROWS / 128, 1);          // (8, 32) = 256 blocks
    hgemm3<false, false, true><<<ogrid, 256, HG_SMEM>>>(
        pA, pWO, out, nullptr, nullptr, nullptr, nullptr, nullptr, nullptr,
        bo, ROWS, D, INNER, 1.0f);
}